// round 15
// baseline (speedup 1.0000x reference)
#include <cuda_runtime.h>
#include <cuda_bf16.h>
#include <cstdint>
#include <cstddef>

// ---------------------------------------------------------------------------
// Problem constants
// ---------------------------------------------------------------------------
#define BATCH   4096
#define IND     512
#define OUTD    512
#define ROWLEN  514            // P + IND
#define D2      25             // D^P
#define KPAD    12800          // IND * D2
#define NCH     200            // 64-wide K chunks, c' = ib*25 + d (ib-major)
#define TILE_M  64
#define TILE_N  64
#define STAGE_B 8192           // B tile per stage: 64 rows x 128B

// smem layout (bytes) for GEMM kernel (104704 total -> 2 CTAs/SM)
#define OFF_BST   0                       // B stages: 4 x 8192 = 32768
#define OFF_XF    32768                   // xf: 8 blocks x 8192 = 65536
#define OFF_KBF   98304                   // kb f32 table: 25*64*4 = 6400
#define SMEM_GEMM 104704

// Packed weight, bf16, K-permuted ib-major:
//   g_W[o][ (ib*25+d)*64 + icol ] = W[i = ib*64+icol][o][d]
__device__ __nv_bfloat16 g_W[(size_t)OUTD * KPAD];

// ---------------------------------------------------------------------------
// PTX helpers (base sm_103 ISA only)
// ---------------------------------------------------------------------------
static __device__ __forceinline__ uint32_t smem_u32(const void* p) {
    uint32_t a;
    asm("{ .reg .u64 t; cvta.to.shared.u64 t, %1; cvt.u32.u64 %0, t; }"
        : "=r"(a) : "l"(p));
    return a;
}

static __device__ __forceinline__ void cp_async16(uint32_t sdst, const void* gsrc) {
    asm volatile("{ .reg .u64 gp; cvta.to.global.u64 gp, %1;"
                 "  cp.async.cg.shared.global [%0], [gp], 16; }"
                 :: "r"(sdst), "l"(gsrc) : "memory");
}

static __device__ __forceinline__ void ldsm_x4(uint32_t* r, uint32_t addr) {
    asm volatile("ldmatrix.sync.aligned.m8n8.x4.shared.b16 {%0,%1,%2,%3}, [%4];"
                 : "=r"(r[0]), "=r"(r[1]), "=r"(r[2]), "=r"(r[3]) : "r"(addr));
}

static __device__ __forceinline__ uint32_t mul_bf16x2(uint32_t a, uint32_t b) {
    uint32_t r;
    asm("mul.rn.bf16x2 %0, %1, %2;" : "=r"(r) : "r"(a), "r"(b));
    return r;
}

static __device__ __forceinline__ void mma16816(float* c, const uint32_t* a,
                                                uint32_t b0, uint32_t b1) {
    asm volatile(
        "mma.sync.aligned.m16n8k16.row.col.f32.bf16.bf16.f32 "
        "{%0,%1,%2,%3}, {%4,%5,%6,%7}, {%8,%9}, {%0,%1,%2,%3};"
        : "+f"(c[0]), "+f"(c[1]), "+f"(c[2]), "+f"(c[3])
        : "r"(a[0]), "r"(a[1]), "r"(a[2]), "r"(a[3]), "r"(b0), "r"(b1));
}

static __device__ __forceinline__ uint16_t f2bf(float f) {
    __nv_bfloat16 h = __float2bfloat16(f);
    return *reinterpret_cast<uint16_t*>(&h);
}

// pack_W smem swizzle: XOR byte-offset bits [4:6] with (pair>>2)&7
static __device__ __forceinline__ uint32_t pk_swz(uint32_t off, int pair) {
    return off ^ (uint32_t)(((pair >> 2) & 7) << 4);
}

// ---------------------------------------------------------------------------
// Kernel 1: coalesced pack of weight (IND,OUTD,25) -> g_W (ib-major K)
// grid = (32 i-blocks of 16, 4 o-blocks of 128), block = 512
// ---------------------------------------------------------------------------
__global__ void __launch_bounds__(512, 1)
pack_W_kernel(const float* __restrict__ w)
{
    extern __shared__ char sc[];           // 3200 pairs x 32B, bank-swizzled
    const int t  = threadIdx.x;
    const int i0 = blockIdx.x * 16;
    const int o0 = blockIdx.y * 128;
    const int ib   = i0 >> 6;              // 16-block never crosses a 64-boundary
    const int icol = i0 & 63;

    // Load: per i, w[(i0+i)*512 + o0 ...] = 3200 contiguous floats, coalesced.
#pragma unroll 1
    for (int i = 0; i < 16; ++i) {
        const float4* src = reinterpret_cast<const float4*>(
            w + ((size_t)(i0 + i) * OUTD + o0) * D2);
        for (int f = t; f < 800; f += 512) {
            const float4 v = src[f];
            const int e0 = f * 4;
#pragma unroll
            for (int q = 0; q < 4; ++q) {
                const int pair = e0 + q;                 // o*25+d
                const float val = (q == 0) ? v.x : (q == 1) ? v.y
                                 : (q == 2) ? v.z : v.w;
                const uint32_t off = pk_swz((uint32_t)pair * 32 + i * 2, pair);
                *reinterpret_cast<__nv_bfloat16*>(sc + off) = __float2bfloat16(val);
            }
        }
    }
    __syncthreads();

    // Store: each (o,d) pair owns 16 bf16 = 32B = two uint4 units.
    for (int p = t; p < 128 * 25 * 2; p += 512) {
        const int pair = p >> 1;
        const int hi   = p & 1;
        const int o = pair / 25;
        const int d = pair - o * 25;
        const uint32_t off = pk_swz((uint32_t)pair * 32 + hi * 16, pair);
        const uint4 v = *reinterpret_cast<const uint4*>(sc + off);
        *reinterpret_cast<uint4*>(
            g_W + (size_t)(o0 + o) * KPAD +
            (ib * 25 + d) * 64 + icol + hi * 8) = v;
    }
}

// ---------------------------------------------------------------------------
// Kernel 2: factorized-A HMMA GEMM, ib-major K, 64x64 tiles, 256 threads,
// TWO CTAs RESIDENT PER SM (smem 104.7KB). RACE-FREE pipeline ordering:
//   wait_group(0) -> __syncthreads -> prefetch e+2,e+3 -> consume e,e+1
// (cp.async wait is per-thread; the barrier AFTER the wait is what makes
// other threads' copies visible before fragment reads — R11-R14 had it
// after the consume, a latent RAW race that fired under 2-CTA pressure.)
// grid = (64, 8), block = 256
// ---------------------------------------------------------------------------
__global__ void __launch_bounds__(256, 2)
gemm_hmma_kernel(const float* __restrict__ x, const float* __restrict__ bias,
                 float* __restrict__ out)
{
    extern __shared__ char smem[];
    const uint32_t sb = smem_u32(smem);
    const int tid  = threadIdx.x;
    const int wid  = tid >> 5;
    const int lid  = tid & 31;
    const int m0   = blockIdx.x * TILE_M;
    const int n0   = blockIdx.y * TILE_N;
    const int wm   = wid >> 2;       // 0..1  (32-row band)
    const int wn   = wid & 3;        // 0..3  (16-col band)

    // ======================= prologue: build smem state =====================
    // xf: 64 rows x 512 cols bf16 as 8 blocks [ib][row][64 cols], SW128.
    for (int f = tid; f < 64 * 256; f += 256) {       // float2 units
        const int row = f >> 8;
        const int c2  = f & 255;
        const int i   = c2 * 2;
        const float2 v = *reinterpret_cast<const float2*>(
            x + (size_t)(m0 + row) * ROWLEN + 2 + i);
        const uint32_t pk = (uint32_t)f2bf(v.x) | ((uint32_t)f2bf(v.y) << 16);
        const int ib = i >> 6;
        const int cb = i & 63;
        const uint32_t off = OFF_XF + ib * 8192 + row * 128 +
                             (((uint32_t)(cb * 2)) ^ ((uint32_t)(row & 7) << 4));
        *reinterpret_cast<uint32_t*>(smem + off) = pk;
    }
    // kb f32 table + x_treat passthrough
    if (tid < 64) {
        const float2 tt = *reinterpret_cast<const float2*>(
            x + (size_t)(m0 + tid) * ROWLEN);
        const float t0 = tt.x, t1 = tt.y;
        float u[5], v[5];
        u[0] = 1.0f; u[1] = t0; u[2] = t0 * t0;
        { float a = t0 - 0.33f; a = a > 0 ? a : 0; u[3] = a * a; }
        { float a = t0 - 0.66f; a = a > 0 ? a : 0; u[4] = a * a; }
        v[0] = 1.0f; v[1] = t1; v[2] = t1 * t1;
        { float a = t1 - 0.33f; a = a > 0 ? a : 0; v[3] = a * a; }
        { float a = t1 - 0.66f; a = a > 0 ? a : 0; v[4] = a * a; }

        float* kbf = reinterpret_cast<float*>(smem + OFF_KBF);
#pragma unroll
        for (int i = 0; i < 5; ++i)
#pragma unroll
            for (int j = 0; j < 5; ++j)
                kbf[(i * 5 + j) * 64 + tid] = u[i] * v[j];

        if (blockIdx.y == 0)
            *reinterpret_cast<float2*>(out + (size_t)(m0 + tid) * ROWLEN) = tt;
    }

    // ======================= B producer geometry ============================
    // chunk = 64 rows x 128B = 512 x 16B quanta; 256 thr -> rows pr0, pr0+32.
    const int  pr0 = tid >> 3;                 // 0..31
    const int  pg  = tid & 7;
    const uint32_t psoff0 = (uint32_t)(pr0 * 128) +
                            ((uint32_t)(pg * 16) ^ (uint32_t)((pr0 & 7) << 4));
    const uint32_t psoff1 = (uint32_t)((pr0 + 32) * 128) +
                            ((uint32_t)(pg * 16) ^ (uint32_t)((pr0 & 7) << 4));
    const __nv_bfloat16* gB0 = g_W + (size_t)(n0 + pr0) * KPAD + pg * 8;
    const __nv_bfloat16* gB1 = g_W + (size_t)(n0 + pr0 + 32) * KPAD + pg * 8;

    // consumer geometry (ldmatrix lane addressing, SW128 swizzle)
    const int arow = wm * 32 + (lid & 15);
    const uint32_t a_sz = (uint32_t)((arow & 7) << 4);
    const uint32_t a_k  = (uint32_t)((lid >> 4) * 16);
    const int brow = wn * 16 + ((lid >> 4) << 3) + (lid & 7);
    const uint32_t b_sz = (uint32_t)((lid & 7) << 4);
    const uint32_t b_k  = (uint32_t)(((lid >> 3) & 1) * 16);

    float c[2][2][4];
#pragma unroll
    for (int mt = 0; mt < 2; ++mt)
#pragma unroll
        for (int nt = 0; nt < 2; ++nt)
#pragma unroll
            for (int i = 0; i < 4; ++i) c[mt][nt][i] = 0.0f;

    // prologue: prefetch chunks 0,1 -> stages 0,1 (single commit)
    {
        const uint32_t d0 = sb + OFF_BST;
        cp_async16(d0 + psoff0,           gB0);
        cp_async16(d0 + psoff1,           gB1);
        cp_async16(d0 + STAGE_B + psoff0, gB0 + 64);
        cp_async16(d0 + STAGE_B + psoff1, gB1 + 64);
        asm volatile("cp.async.commit_group;" ::: "memory");
    }

    const float* kbf = reinterpret_cast<const float*>(smem + OFF_KBF);
    const int krow0 = wm * 32 + (lid >> 2);   // fragment row within tile (+mt*16)

    uint32_t xfA[4][2][4];   // raw xf frags [ks][mt][reg], persists across d
    uint32_t aS[2][4];       // scaled frags for current ks
    uint32_t bF[2][4];       // B frags (16 cols x k16), double buffered

#define LOAD_XFA(base)                                                         \
    {   _Pragma("unroll")                                                      \
        for (int ks = 0; ks < 4; ++ks)                                         \
            _Pragma("unroll")                                                  \
            for (int mt = 0; mt < 2; ++mt)                                     \
                ldsm_x4(xfA[ks][mt], (base) + (uint32_t)(arow + mt * 16) * 128 \
                        + (((uint32_t)(ks * 32) + a_k) ^ a_sz));               \
    }

#define LOAD_B(buf, kk)                                                        \
    {   const uint32_t kof = (uint32_t)((kk) * 32);                            \
        ldsm_x4(bF[buf], stB + (uint32_t)brow * 128 + ((kof + b_k) ^ b_sz));   \
    }

// consume one 64-K chunk from stage (f&3); d/ib tracked by caller counters
#define CONSUME(f, dcur, ibcur)                                                \
    {   const uint32_t stB = sb + OFF_BST + ((f) & 3) * STAGE_B;               \
        if ((dcur) == 0) LOAD_XFA(sb + OFF_XF + (uint32_t)(ibcur) * 8192);     \
        uint32_t kLo[2], kHi[2];                                               \
        _Pragma("unroll")                                                      \
        for (int mt = 0; mt < 2; ++mt) {                                       \
            const int r = krow0 + mt * 16;                                     \
            kLo[mt] = (uint32_t)f2bf(kbf[(dcur) * 64 + r]) * 0x10001u;         \
            kHi[mt] = (uint32_t)f2bf(kbf[(dcur) * 64 + r + 8]) * 0x10001u;     \
        }                                                                      \
        LOAD_B(0, 0);                                                          \
        _Pragma("unroll")                                                      \
        for (int ks = 0; ks < 4; ++ks) {                                       \
            const int cur = ks & 1;                                            \
            if (ks < 3) LOAD_B(cur ^ 1, ks + 1);                               \
            _Pragma("unroll")                                                  \
            for (int mt = 0; mt < 2; ++mt) {                                   \
                aS[mt][0] = mul_bf16x2(xfA[ks][mt][0], kLo[mt]);               \
                aS[mt][1] = mul_bf16x2(xfA[ks][mt][1], kHi[mt]);               \
                aS[mt][2] = mul_bf16x2(xfA[ks][mt][2], kLo[mt]);               \
                aS[mt][3] = mul_bf16x2(xfA[ks][mt][3], kHi[mt]);               \
            }                                                                  \
            _Pragma("unroll")                                                  \
            for (int mt = 0; mt < 2; ++mt) {                                   \
                mma16816(c[mt][0], aS[mt], bF[cur][0], bF[cur][1]);            \
                mma16816(c[mt][1], aS[mt], bF[cur][2], bF[cur][3]);            \
            }                                                                  \
        }                                                                      \
    }

    int dcnt = 0, ibc = 0;

    // === main loop: RACE-FREE ordering, 1 barrier/epoch =====================
    // wait(0): this thread's chunks e,e+1 landed; barrier: EVERYONE's landed.
    // Prefetch (stages e+2,e+3) is disjoint from this epoch's reads; next
    // epoch's top barrier protects its reads; epoch-e reads precede the
    // epoch-(e+2) top barrier, so its writes to stage e&3 cannot race them.
    for (int e = 0; e < NCH; e += 2) {
        asm volatile("cp.async.wait_group 0;" ::: "memory");
        __syncthreads();

#pragma unroll
        for (int k = 2; k < 4; ++k) {
            const int f = e + k;
            if (f < NCH) {
                const uint32_t dst = sb + OFF_BST + (f & 3) * STAGE_B;
                cp_async16(dst + psoff0, gB0 + (size_t)f * 64);
                cp_async16(dst + psoff1, gB1 + (size_t)f * 64);
            }
        }
        asm volatile("cp.async.commit_group;" ::: "memory");

        CONSUME(e, dcnt, ibc);
        if (++dcnt == D2) { dcnt = 0; ++ibc; }
        CONSUME(e + 1, dcnt, ibc);
        if (++dcnt == D2) { dcnt = 0; ++ibc; }
    }

    // ================= bias epilogue: c += kb(f32) @ bias^T =================
    asm volatile("cp.async.wait_group 0;" ::: "memory");
    __syncthreads();   // all fragment reads done before sbias overwrites stage 0
    float* sbias = reinterpret_cast<float*>(smem + OFF_BST);
    {
        const float* gb = bias + (size_t)n0 * D2;
        for (int i = tid; i < 64 * D2; i += 256) sbias[i] = gb[i];
    }
    __syncthreads();

    {
        const int cb0 = wn * 16 + ((lid & 3) << 1);   // local col base
#pragma unroll 1
        for (int d = 0; d < D2; ++d) {
            float kbA[2], kbB[2];
#pragma unroll
            for (int mt = 0; mt < 2; ++mt) {
                const int r = krow0 + mt * 16;
                kbA[mt] = kbf[d * 64 + r];
                kbB[mt] = kbf[d * 64 + r + 8];
            }
#pragma unroll
            for (int nt = 0; nt < 2; ++nt) {
                const int cc = cb0 + nt * 8;
                const float b0 = sbias[cc * D2 + d];
                const float b1 = sbias[(cc + 1) * D2 + d];
#pragma unroll
                for (int mt = 0; mt < 2; ++mt) {
                    c[mt][nt][0] += kbA[mt] * b0;
                    c[mt][nt][1] += kbA[mt] * b1;
                    c[mt][nt][2] += kbB[mt] * b0;
                    c[mt][nt][3] += kbB[mt] * b1;
                }
            }
        }
    }

    // ---- fused ReLU epilogue
    {
        const int rbase = m0 + wm * 32 + (lid >> 2);
        const int cbase = n0 + wn * 16 + ((lid & 3) << 1);
#pragma unroll
        for (int mt = 0; mt < 2; ++mt) {
            const int r = rbase + mt * 16;
#pragma unroll
            for (int nt = 0; nt < 2; ++nt) {
                const int cc = cbase + nt * 8;
                float2 v0, v1;
                v0.x = fmaxf(c[mt][nt][0], 0.0f);
                v0.y = fmaxf(c[mt][nt][1], 0.0f);
                v1.x = fmaxf(c[mt][nt][2], 0.0f);
                v1.y = fmaxf(c[mt][nt][3], 0.0f);
                *reinterpret_cast<float2*>(out + (size_t)r * ROWLEN + 2 + cc) = v0;
                *reinterpret_cast<float2*>(out + (size_t)(r + 8) * ROWLEN + 2 + cc) = v1;
            }
        }
    }
}

// ---------------------------------------------------------------------------
// Launch
// ---------------------------------------------------------------------------
extern "C" void kernel_launch(void* const* d_in, const int* in_sizes, int n_in,
                              void* d_out, int out_size)
{
    (void)in_sizes; (void)n_in; (void)out_size;
    const float* x    = (const float*)d_in[0];   // (4096, 514)
    const float* w    = (const float*)d_in[1];   // (512, 512, 25)
    const float* bias = (const float*)d_in[2];   // (512, 25)
    float* out = (float*)d_out;                  // (4096, 514)

    cudaFuncSetAttribute(pack_W_kernel,
                         cudaFuncAttributeMaxDynamicSharedMemorySize, 102400);
    cudaFuncSetAttribute(gemm_hmma_kernel,
                         cudaFuncAttributeMaxDynamicSharedMemorySize, SMEM_GEMM);

    pack_W_kernel<<<dim3(32, 4), 512, 102400>>>(w);
    gemm_hmma_kernel<<<dim3(BATCH / TILE_M, OUTD / TILE_N), 256, SMEM_GEMM>>>(
        x, bias, out);
}

// round 16
// speedup vs baseline: 1.2218x; 1.2218x over previous
#include <cuda_runtime.h>
#include <cuda_bf16.h>
#include <cstdint>
#include <cstddef>

// ---------------------------------------------------------------------------
// Problem constants
// ---------------------------------------------------------------------------
#define BATCH   4096
#define IND     512
#define OUTD    512
#define ROWLEN  514            // P + IND
#define D2      25             // D^P
#define KPAD    12800          // IND * D2
#define NCH     200            // 64-wide K chunks, c' = ib*25 + d (ib-major)
#define TILE_M  128
#define TILE_N  128
#define STAGE_B 16384          // B tile per stage: 128 rows x 128B

// smem layout (bytes): B 8 stages + xf 2 staging blocks + kb tables = 183040
#define OFF_BST   0                       // B stages: 8 x 16384 = 131072
#define OFF_XF    131072                  // xf staging: 2 x 16384 = 32768
#define OFF_KBF   163840                  // kb f32 table: 25*128*4 = 12800
#define OFF_KBS   176640                  // kb bf16 table: 25*128*2 = 6400
#define SMEM_GEMM 183040

// Packed weight, bf16, K-permuted ib-major:
//   g_W[o][ (ib*25+d)*64 + icol ] = W[i = ib*64+icol][o][d]
__device__ __nv_bfloat16 g_W[(size_t)OUTD * KPAD];
// x features pre-converted to bf16: g_XF[b][i]  (4 MB)
__device__ __nv_bfloat16 g_XF[(size_t)BATCH * IND];

// ---------------------------------------------------------------------------
// PTX helpers (base sm_103 ISA only)
// ---------------------------------------------------------------------------
static __device__ __forceinline__ uint32_t smem_u32(const void* p) {
    uint32_t a;
    asm("{ .reg .u64 t; cvta.to.shared.u64 t, %1; cvt.u32.u64 %0, t; }"
        : "=r"(a) : "l"(p));
    return a;
}

static __device__ __forceinline__ void cp_async16(uint32_t sdst, const void* gsrc) {
    asm volatile("{ .reg .u64 gp; cvta.to.global.u64 gp, %1;"
                 "  cp.async.cg.shared.global [%0], [gp], 16; }"
                 :: "r"(sdst), "l"(gsrc) : "memory");
}

static __device__ __forceinline__ void ldsm_x4(uint32_t* r, uint32_t addr) {
    asm volatile("ldmatrix.sync.aligned.m8n8.x4.shared.b16 {%0,%1,%2,%3}, [%4];"
                 : "=r"(r[0]), "=r"(r[1]), "=r"(r[2]), "=r"(r[3]) : "r"(addr));
}

static __device__ __forceinline__ uint32_t mul_bf16x2(uint32_t a, uint32_t b) {
    uint32_t r;
    asm("mul.rn.bf16x2 %0, %1, %2;" : "=r"(r) : "r"(a), "r"(b));
    return r;
}

static __device__ __forceinline__ void mma16816(float* c, const uint32_t* a,
                                                uint32_t b0, uint32_t b1) {
    asm volatile(
        "mma.sync.aligned.m16n8k16.row.col.f32.bf16.bf16.f32 "
        "{%0,%1,%2,%3}, {%4,%5,%6,%7}, {%8,%9}, {%0,%1,%2,%3};"
        : "+f"(c[0]), "+f"(c[1]), "+f"(c[2]), "+f"(c[3])
        : "r"(a[0]), "r"(a[1]), "r"(a[2]), "r"(a[3]), "r"(b0), "r"(b1));
}

static __device__ __forceinline__ uint16_t f2bf(float f) {
    __nv_bfloat16 h = __float2bfloat16(f);
    return *reinterpret_cast<uint16_t*>(&h);
}

// pack_W smem swizzle: XOR byte-offset bits [4:6] with (pair>>2)&7
static __device__ __forceinline__ uint32_t pk_swz(uint32_t off, int pair) {
    return off ^ (uint32_t)(((pair >> 2) & 7) << 4);
}

// ---------------------------------------------------------------------------
// Kernel 0: x features f32 -> bf16 (g_XF), x_treat passthrough to out.
// grid = 4096, block = 128
// ---------------------------------------------------------------------------
__global__ void __launch_bounds__(128, 1)
prep_XF_kernel(const float* __restrict__ x, float* __restrict__ out)
{
    const int b = blockIdx.x;
    const int t = threadIdx.x;
    const float* xr = x + (size_t)b * ROWLEN;
    if (t < 2) out[(size_t)b * ROWLEN + t] = xr[t];
    uint32_t* dst = reinterpret_cast<uint32_t*>(g_XF + (size_t)b * IND);
#pragma unroll
    for (int j = 0; j < 2; ++j) {
        const int u = t + j * 128;              // float2 unit 0..255
        const float2 v = *reinterpret_cast<const float2*>(xr + 2 + u * 2);
        dst[u] = (uint32_t)f2bf(v.x) | ((uint32_t)f2bf(v.y) << 16);
    }
}

// ---------------------------------------------------------------------------
// Kernel 1: coalesced pack of weight (IND,OUTD,25) -> g_W (ib-major K)
// grid = (32 i-blocks of 16, 4 o-blocks of 128), block = 512
// ---------------------------------------------------------------------------
__global__ void __launch_bounds__(512, 1)
pack_W_kernel(const float* __restrict__ w)
{
    extern __shared__ char sc[];           // 3200 pairs x 32B, bank-swizzled
    const int t  = threadIdx.x;
    const int i0 = blockIdx.x * 16;
    const int o0 = blockIdx.y * 128;
    const int ib   = i0 >> 6;
    const int icol = i0 & 63;

#pragma unroll 1
    for (int i = 0; i < 16; ++i) {
        const float4* src = reinterpret_cast<const float4*>(
            w + ((size_t)(i0 + i) * OUTD + o0) * D2);
        for (int f = t; f < 800; f += 512) {
            const float4 v = src[f];
            const int e0 = f * 4;
#pragma unroll
            for (int q = 0; q < 4; ++q) {
                const int pair = e0 + q;                 // o*25+d
                const float val = (q == 0) ? v.x : (q == 1) ? v.y
                                 : (q == 2) ? v.z : v.w;
                const uint32_t off = pk_swz((uint32_t)pair * 32 + i * 2, pair);
                *reinterpret_cast<__nv_bfloat16*>(sc + off) = __float2bfloat16(val);
            }
        }
    }
    __syncthreads();

    for (int p = t; p < 128 * 25 * 2; p += 512) {
        const int pair = p >> 1;
        const int hi   = p & 1;
        const int o = pair / 25;
        const int d = pair - o * 25;
        const uint32_t off = pk_swz((uint32_t)pair * 32 + hi * 16, pair);
        const uint4 v = *reinterpret_cast<const uint4*>(sc + off);
        *reinterpret_cast<uint4*>(
            g_W + (size_t)(o0 + o) * KPAD +
            (ib * 25 + d) * 64 + icol + hi * 8) = v;
    }
}

// ---------------------------------------------------------------------------
// Kernel 2: factorized-A HMMA GEMM, ib-major K, 128x128 tile, 512 threads,
// 4x4 warp grid (32x32 warp tiles). RACE-FREE epoch ordering:
//   wait_group(0) -> __syncthreads -> prefetch -> consume x4
// 4 chunks/epoch (50 barriers), 8 B-stages. xf staged in a double-buffered
// smem pair, cp.async-prefetched one ib ahead from g_XF; raw xf fragments
// register-resident per ib. Bias in f32 FFMA epilogue, fused ReLU.
// grid = (32, 4), block = 512
// ---------------------------------------------------------------------------
__global__ void __launch_bounds__(512, 1)
gemm_hmma_kernel(const float* __restrict__ x, const float* __restrict__ bias,
                 float* __restrict__ out)
{
    extern __shared__ char smem[];
    const uint32_t sb = smem_u32(smem);
    const int tid  = threadIdx.x;
    const int wid  = tid >> 5;
    const int lid  = tid & 31;
    const int m0   = blockIdx.x * TILE_M;
    const int n0   = blockIdx.y * TILE_N;
    const int wm   = wid >> 2;       // 0..3  (32-row band)
    const int wn   = wid & 3;        // 0..3  (32-col band)

    // ======================= producer geometry ==============================
    const int  pr0 = tid >> 3;                 // 0..63
    const int  pg  = tid & 7;
    const uint32_t swz = (uint32_t)(pg * 16) ^ (uint32_t)((pr0 & 7) << 4);
    const uint32_t psoff0 = (uint32_t)(pr0 * 128) + swz;
    const uint32_t psoff1 = (uint32_t)((pr0 + 64) * 128) + swz;
    const __nv_bfloat16* gB0 = g_W + (size_t)(n0 + pr0) * KPAD + pg * 8;
    const __nv_bfloat16* gB1 = g_W + (size_t)(n0 + pr0 + 64) * KPAD + pg * 8;
    const __nv_bfloat16* gX0 = g_XF + (size_t)(m0 + pr0) * IND + pg * 8;
    const __nv_bfloat16* gX1 = g_XF + (size_t)(m0 + pr0 + 64) * IND + pg * 8;

// prefetch xf block (ibn) into parity slot (ibn&1)
#define PREFETCH_XF(ibn)                                                       \
    {   const uint32_t dstb = sb + OFF_XF + (uint32_t)(((ibn) & 1) * 16384);   \
        cp_async16(dstb + psoff0, gX0 + (ibn) * 64);                           \
        cp_async16(dstb + psoff1, gX1 + (ibn) * 64);                           \
    }

    // prologue: B chunks 0..3 -> stages 0..3, xf blocks 0,1 -> parities 0,1
#pragma unroll
    for (int f = 0; f < 4; ++f) {
        const uint32_t dst = sb + OFF_BST + f * STAGE_B;
        cp_async16(dst + psoff0, gB0 + (size_t)f * 64);
        cp_async16(dst + psoff1, gB1 + (size_t)f * 64);
    }
    PREFETCH_XF(0);
    PREFETCH_XF(1);
    asm volatile("cp.async.commit_group;" ::: "memory");

    // kb tables (f32 for epilogue, bf16 for mainloop scales)
    if (tid < 128) {
        const float2 tt = *reinterpret_cast<const float2*>(
            x + (size_t)(m0 + tid) * ROWLEN);
        const float t0 = tt.x, t1 = tt.y;
        float u[5], v[5];
        u[0] = 1.0f; u[1] = t0; u[2] = t0 * t0;
        { float a = t0 - 0.33f; a = a > 0 ? a : 0; u[3] = a * a; }
        { float a = t0 - 0.66f; a = a > 0 ? a : 0; u[4] = a * a; }
        v[0] = 1.0f; v[1] = t1; v[2] = t1 * t1;
        { float a = t1 - 0.33f; a = a > 0 ? a : 0; v[3] = a * a; }
        { float a = t1 - 0.66f; a = a > 0 ? a : 0; v[4] = a * a; }

        float* kbf = reinterpret_cast<float*>(smem + OFF_KBF);
        uint16_t* kbs = reinterpret_cast<uint16_t*>(smem + OFF_KBS);
#pragma unroll
        for (int i = 0; i < 5; ++i)
#pragma unroll
            for (int j = 0; j < 5; ++j) {
                const int d = i * 5 + j;
                const float kv = u[i] * v[j];
                kbf[d * 128 + tid] = kv;
                kbs[d * 128 + tid] = f2bf(kv);
            }
    }

    // ======================= consumer geometry ==============================
    const int arow = wm * 32 + (lid & 15);
    const uint32_t a_sz = (uint32_t)((arow & 7) << 4);
    const uint32_t a_k  = (uint32_t)((lid >> 4) * 16);
    const int brow = wn * 32 + ((lid >> 4) << 3) + (lid & 7);
    const uint32_t b_sz = (uint32_t)((lid & 7) << 4);
    const uint32_t b_k  = (uint32_t)(((lid >> 3) & 1) * 16);

    float c[2][4][4];
#pragma unroll
    for (int mt = 0; mt < 2; ++mt)
#pragma unroll
        for (int nt = 0; nt < 4; ++nt)
#pragma unroll
            for (int i = 0; i < 4; ++i) c[mt][nt][i] = 0.0f;

    const float*    kbf = reinterpret_cast<const float*>(smem + OFF_KBF);
    const uint16_t* kbs = reinterpret_cast<const uint16_t*>(smem + OFF_KBS);
    const int krow0 = wm * 32 + (lid >> 2);   // fragment row (+mt*16)

    uint32_t xfA[4][2][4];   // raw xf frags [ks][mt][reg], persists across d
    uint32_t aS[2][4];       // scaled frags for current ks
    uint32_t bF[2][2][4];    // B frags, double buffered

#define LOAD_XFA(ibcur)                                                        \
    {   const uint32_t base = sb + OFF_XF + (uint32_t)(((ibcur) & 1) * 16384); \
        _Pragma("unroll")                                                      \
        for (int ks = 0; ks < 4; ++ks)                                         \
            _Pragma("unroll")                                                  \
            for (int mt = 0; mt < 2; ++mt)                                     \
                ldsm_x4(xfA[ks][mt], base + (uint32_t)(arow + mt * 16) * 128   \
                        + (((uint32_t)(ks * 32) + a_k) ^ a_sz));               \
    }

#define LOAD_B(buf, kk)                                                        \
    {   const uint32_t kof = (uint32_t)((kk) * 32);                            \
        _Pragma("unroll")                                                      \
        for (int np = 0; np < 2; ++np)                                         \
            ldsm_x4(bF[buf][np], stB + (uint32_t)(brow + np * 16) * 128 +      \
                                 ((kof + b_k) ^ b_sz));                        \
    }

#define CONSUME(f, dcur, ibcur)                                                \
    {   const uint32_t stB = sb + OFF_BST + ((f) & 7) * STAGE_B;               \
        if ((dcur) == 0) LOAD_XFA(ibcur);                                      \
        uint32_t kLo[2], kHi[2];                                               \
        _Pragma("unroll")                                                      \
        for (int mt = 0; mt < 2; ++mt) {                                       \
            const int r = krow0 + mt * 16;                                     \
            kLo[mt] = (uint32_t)kbs[(dcur) * 128 + r] * 0x10001u;              \
            kHi[mt] = (uint32_t)kbs[(dcur) * 128 + r + 8] * 0x10001u;          \
        }                                                                      \
        LOAD_B(0, 0);                                                          \
        _Pragma("unroll")                                                      \
        for (int ks = 0; ks < 4; ++ks) {                                       \
            const int cur = ks & 1;                                            \
            if (ks < 3) LOAD_B(cur ^ 1, ks + 1);                               \
            _Pragma("unroll")                                                  \
            for (int mt = 0; mt < 2; ++mt) {                                   \
                aS[mt][0] = mul_bf16x2(xfA[ks][mt][0], kLo[mt]);               \
                aS[mt][1] = mul_bf16x2(xfA[ks][mt][1], kHi[mt]);               \
                aS[mt][2] = mul_bf16x2(xfA[ks][mt][2], kLo[mt]);               \
                aS[mt][3] = mul_bf16x2(xfA[ks][mt][3], kHi[mt]);               \
            }                                                                  \
            _Pragma("unroll")                                                  \
            for (int mt = 0; mt < 2; ++mt)                                     \
                _Pragma("unroll")                                              \
                for (int np = 0; np < 2; ++np) {                               \
                    mma16816(c[mt][2*np],   aS[mt], bF[cur][np][0], bF[cur][np][1]); \
                    mma16816(c[mt][2*np+1], aS[mt], bF[cur][np][2], bF[cur][np][3]); \
                }                                                              \
        }                                                                      \
    }

    int dcnt = 0, ibc = 0, ibp = 1;

    // === main loop: 4 chunks/epoch, RACE-FREE ordering, 50 barriers =========
    // wait(0)+barrier: ALL threads' pending copies visible before any read.
    // Epoch e reads stages e..e+3 (&7) and xf parities of current ib(s);
    // writes stages e+4..e+7 (&7) and (rarely) xf parity of ib 2 ahead of
    // any live read — disjoint. Next epoch's barrier protects its reads.
    for (int e = 0; e < NCH; e += 4) {
        asm volatile("cp.async.wait_group 0;" ::: "memory");
        __syncthreads();

#pragma unroll
        for (int k = 4; k < 8; ++k) {
            const int f = e + k;
            if (f < NCH) {
                const uint32_t dst = sb + OFF_BST + (f & 7) * STAGE_B;
                cp_async16(dst + psoff0, gB0 + (size_t)f * 64);
                cp_async16(dst + psoff1, gB1 + (size_t)f * 64);
            }
        }
        {   // xf block needed next epoch (chunks e+4..e+7): at most one new ib
            const int ibn = (e + 7) / 25;
            if (ibn > ibp && ibn < 8) { PREFETCH_XF(ibn); ibp = ibn; }
        }
        asm volatile("cp.async.commit_group;" ::: "memory");

        CONSUME(e,     dcnt, ibc); if (++dcnt == D2) { dcnt = 0; ++ibc; }
        CONSUME(e + 1, dcnt, ibc); if (++dcnt == D2) { dcnt = 0; ++ibc; }
        CONSUME(e + 2, dcnt, ibc); if (++dcnt == D2) { dcnt = 0; ++ibc; }
        CONSUME(e + 3, dcnt, ibc); if (++dcnt == D2) { dcnt = 0; ++ibc; }
    }

    // ================= bias epilogue: c += kb(f32) @ bias^T =================
    asm volatile("cp.async.wait_group 0;" ::: "memory");
    __syncthreads();   // all fragment reads done before sbias overwrites stage 0
    float* sbias = reinterpret_cast<float*>(smem + OFF_BST);
    {
        const float* gb = bias + (size_t)n0 * D2;
        for (int i = tid; i < 128 * D2; i += 512) sbias[i] = gb[i];
    }
    __syncthreads();

    {
        const int cb0 = wn * 32 + ((lid & 3) << 1);   // local col base
#pragma unroll 1
        for (int d = 0; d < D2; ++d) {
            float kbA[2], kbB[2];
#pragma unroll
            for (int mt = 0; mt < 2; ++mt) {
                const int r = krow0 + mt * 16;
                kbA[mt] = kbf[d * 128 + r];
                kbB[mt] = kbf[d * 128 + r + 8];
            }
#pragma unroll
            for (int nt = 0; nt < 4; ++nt) {
                const int cc = cb0 + nt * 8;
                const float b0 = sbias[cc * D2 + d];
                const float b1 = sbias[(cc + 1) * D2 + d];
#pragma unroll
                for (int mt = 0; mt < 2; ++mt) {
                    c[mt][nt][0] += kbA[mt] * b0;
                    c[mt][nt][1] += kbA[mt] * b1;
                    c[mt][nt][2] += kbB[mt] * b0;
                    c[mt][nt][3] += kbB[mt] * b1;
                }
            }
        }
    }

    // ---- fused ReLU epilogue
    {
        const int rbase = m0 + wm * 32 + (lid >> 2);
        const int cbase = n0 + wn * 32 + ((lid & 3) << 1);
#pragma unroll
        for (int mt = 0; mt < 2; ++mt) {
            const int r = rbase + mt * 16;
#pragma unroll
            for (int nt = 0; nt < 4; ++nt) {
                const int cc = cbase + nt * 8;
                float2 v0, v1;
                v0.x = fmaxf(c[mt][nt][0], 0.0f);
                v0.y = fmaxf(c[mt][nt][1], 0.0f);
                v1.x = fmaxf(c[mt][nt][2], 0.0f);
                v1.y = fmaxf(c[mt][nt][3], 0.0f);
                *reinterpret_cast<float2*>(out + (size_t)r * ROWLEN + 2 + cc) = v0;
                *reinterpret_cast<float2*>(out + (size_t)(r + 8) * ROWLEN + 2 + cc) = v1;
            }
        }
    }
}

// ---------------------------------------------------------------------------
// Launch
// ---------------------------------------------------------------------------
extern "C" void kernel_launch(void* const* d_in, const int* in_sizes, int n_in,
                              void* d_out, int out_size)
{
    (void)in_sizes; (void)n_in; (void)out_size;
    const float* x    = (const float*)d_in[0];   // (4096, 514)
    const float* w    = (const float*)d_in[1];   // (512, 512, 25)
    const float* bias = (const float*)d_in[2];   // (512, 25)
    float* out = (float*)d_out;                  // (4096, 514)

    cudaFuncSetAttribute(pack_W_kernel,
                         cudaFuncAttributeMaxDynamicSharedMemorySize, 102400);
    cudaFuncSetAttribute(gemm_hmma_kernel,
                         cudaFuncAttributeMaxDynamicSharedMemorySize, SMEM_GEMM);

    prep_XF_kernel<<<BATCH, 128>>>(x, out);
    pack_W_kernel<<<dim3(32, 4), 512, 102400>>>(w);
    gemm_hmma_kernel<<<dim3(BATCH / TILE_M, OUTD / TILE_N), 512, SMEM_GEMM>>>(
        x, bias, out);
}

// round 17
// speedup vs baseline: 1.2522x; 1.0249x over previous
#include <cuda_runtime.h>
#include <cuda_bf16.h>
#include <cstdint>
#include <cstddef>

// ---------------------------------------------------------------------------
// Problem constants
// ---------------------------------------------------------------------------
#define BATCH   4096
#define IND     512
#define OUTD    512
#define ROWLEN  514            // P + IND
#define D2      25             // D^P
#define KPAD    12800          // IND * D2
#define NCH     200            // 64-wide K chunks, c' = ib*25 + d (ib-major)
#define TILE_M  128
#define TILE_N  128
#define STAGE_B 16384          // B tile per stage: 128 rows x 128B

// smem layout (bytes): B 8 stages + xf 2 staging blocks + kb tables = 183040
// (the pack scratch, 102400B, overlays the B-stage area before the pipeline)
#define OFF_BST   0                       // B stages: 8 x 16384 = 131072
#define OFF_XF    131072                  // xf staging: 2 x 16384 = 32768
#define OFF_KBF   163840                  // kb f32 table: 25*128*4 = 12800
#define OFF_KBS   176640                  // kb bf16 table: 25*128*2 = 6400
#define SMEM_GEMM 183040

// Packed weight, bf16, K-permuted ib-major:
//   g_W[o][ (ib*25+d)*64 + icol ] = W[i = ib*64+icol][o][d]
__device__ __nv_bfloat16 g_W[(size_t)OUTD * KPAD];
// x features pre-converted to bf16: g_XF[b][i]  (4 MB)
__device__ __nv_bfloat16 g_XF[(size_t)BATCH * IND];
// per-o-block pack completion counters (zeroed by prep_XF each invocation)
__device__ unsigned g_cnt[4];

// ---------------------------------------------------------------------------
// PTX helpers (base sm_103 ISA only)
// ---------------------------------------------------------------------------
static __device__ __forceinline__ uint32_t smem_u32(const void* p) {
    uint32_t a;
    asm("{ .reg .u64 t; cvta.to.shared.u64 t, %1; cvt.u32.u64 %0, t; }"
        : "=r"(a) : "l"(p));
    return a;
}

static __device__ __forceinline__ void cp_async16(uint32_t sdst, const void* gsrc) {
    asm volatile("{ .reg .u64 gp; cvta.to.global.u64 gp, %1;"
                 "  cp.async.cg.shared.global [%0], [gp], 16; }"
                 :: "r"(sdst), "l"(gsrc) : "memory");
}

static __device__ __forceinline__ void ldsm_x4(uint32_t* r, uint32_t addr) {
    asm volatile("ldmatrix.sync.aligned.m8n8.x4.shared.b16 {%0,%1,%2,%3}, [%4];"
                 : "=r"(r[0]), "=r"(r[1]), "=r"(r[2]), "=r"(r[3]) : "r"(addr));
}

static __device__ __forceinline__ uint32_t mul_bf16x2(uint32_t a, uint32_t b) {
    uint32_t r;
    asm("mul.rn.bf16x2 %0, %1, %2;" : "=r"(r) : "r"(a), "r"(b));
    return r;
}

static __device__ __forceinline__ void mma16816(float* c, const uint32_t* a,
                                                uint32_t b0, uint32_t b1) {
    asm volatile(
        "mma.sync.aligned.m16n8k16.row.col.f32.bf16.bf16.f32 "
        "{%0,%1,%2,%3}, {%4,%5,%6,%7}, {%8,%9}, {%0,%1,%2,%3};"
        : "+f"(c[0]), "+f"(c[1]), "+f"(c[2]), "+f"(c[3])
        : "r"(a[0]), "r"(a[1]), "r"(a[2]), "r"(a[3]), "r"(b0), "r"(b1));
}

static __device__ __forceinline__ uint16_t f2bf(float f) {
    __nv_bfloat16 h = __float2bfloat16(f);
    return *reinterpret_cast<uint16_t*>(&h);
}

// pack smem swizzle: XOR byte-offset bits [4:6] with (pair>>2)&7
static __device__ __forceinline__ uint32_t pk_swz(uint32_t off, int pair) {
    return off ^ (uint32_t)(((pair >> 2) & 7) << 4);
}

// ---------------------------------------------------------------------------
// Kernel 0: x features f32 -> bf16 (g_XF), x_treat passthrough, flag reset.
// grid = 4096, block = 256
// ---------------------------------------------------------------------------
__global__ void __launch_bounds__(256, 1)
prep_XF_kernel(const float* __restrict__ x, float* __restrict__ out)
{
    const int b = blockIdx.x;
    const int t = threadIdx.x;
    if (b == 0 && t < 4) g_cnt[t] = 0;        // reset pack counters (per call)
    const float* xr = x + (size_t)b * ROWLEN;
    if (t < 2) out[(size_t)b * ROWLEN + t] = xr[t];
    uint32_t* dst = reinterpret_cast<uint32_t*>(g_XF + (size_t)b * IND);
    const float2 v = *reinterpret_cast<const float2*>(xr + 2 + t * 2);
    dst[t] = (uint32_t)f2bf(v.x) | ((uint32_t)f2bf(v.y) << 16);
}

// ---------------------------------------------------------------------------
// Kernel 1: fused pack + factorized-A HMMA GEMM.
// Phase A: CTA (bx,by) packs W i-block bx / o-block by into g_W (ib-major K),
//          signals g_cnt[by]; kb tables + xf prefetch overlap the pack tail;
//          CTA spins until all 32 i-blocks of its o-block are packed.
// Phase B: R16's GEMM: 128x128 tile, 512 thr, 4x4 warp grid, 4 chunks/epoch,
//          8 B-stages, race-free ordering (wait(0) -> barrier -> prefetch ->
//          consume), register-resident xf per ib, f32 bias epilogue + ReLU.
// grid = (32, 4), block = 512
// ---------------------------------------------------------------------------
__global__ void __launch_bounds__(512, 1)
gemm_hmma_kernel(const float* __restrict__ x, const float* __restrict__ w,
                 const float* __restrict__ bias, float* __restrict__ out)
{
    extern __shared__ char smem[];
    const uint32_t sb = smem_u32(smem);
    const int tid  = threadIdx.x;
    const int wid  = tid >> 5;
    const int lid  = tid & 31;
    const int m0   = blockIdx.x * TILE_M;
    const int n0   = blockIdx.y * TILE_N;
    const int wm   = wid >> 2;       // 0..3  (32-row band)
    const int wn   = wid & 3;        // 0..3  (32-col band)

    // ================== Phase A: pack my W slice into g_W ===================
    {
        char* sc = smem;                       // scratch overlays B-stage area
        const int i0 = blockIdx.x * 16;
        const int o0 = blockIdx.y * 128;
        const int ib   = i0 >> 6;
        const int icol = i0 & 63;

#pragma unroll 1
        for (int i = 0; i < 16; ++i) {
            const float4* src = reinterpret_cast<const float4*>(
                w + ((size_t)(i0 + i) * OUTD + o0) * D2);
            for (int f = tid; f < 800; f += 512) {
                const float4 v = src[f];
                const int e0 = f * 4;
#pragma unroll
                for (int q = 0; q < 4; ++q) {
                    const int pair = e0 + q;             // o*25+d
                    const float val = (q == 0) ? v.x : (q == 1) ? v.y
                                     : (q == 2) ? v.z : v.w;
                    const uint32_t off = pk_swz((uint32_t)pair * 32 + i * 2, pair);
                    *reinterpret_cast<__nv_bfloat16*>(sc + off) = __float2bfloat16(val);
                }
            }
        }
        __syncthreads();

        for (int p = tid; p < 128 * 25 * 2; p += 512) {
            const int pair = p >> 1;
            const int hi   = p & 1;
            const int o = pair / 25;
            const int d = pair - o * 25;
            const uint32_t off = pk_swz((uint32_t)pair * 32 + hi * 16, pair);
            const uint4 v = *reinterpret_cast<const uint4*>(sc + off);
            *reinterpret_cast<uint4*>(
                g_W + (size_t)(o0 + o) * KPAD +
                (ib * 25 + d) * 64 + icol + hi * 8) = v;
        }
        __threadfence();
        __syncthreads();
        if (tid == 0) atomicAdd(&g_cnt[blockIdx.y], 1u);
    }

    // ======================= producer geometry ==============================
    const int  pr0 = tid >> 3;                 // 0..63
    const int  pg  = tid & 7;
    const uint32_t swz = (uint32_t)(pg * 16) ^ (uint32_t)((pr0 & 7) << 4);
    const uint32_t psoff0 = (uint32_t)(pr0 * 128) + swz;
    const uint32_t psoff1 = (uint32_t)((pr0 + 64) * 128) + swz;
    const __nv_bfloat16* gB0 = g_W + (size_t)(n0 + pr0) * KPAD + pg * 8;
    const __nv_bfloat16* gB1 = g_W + (size_t)(n0 + pr0 + 64) * KPAD + pg * 8;
    const __nv_bfloat16* gX0 = g_XF + (size_t)(m0 + pr0) * IND + pg * 8;
    const __nv_bfloat16* gX1 = g_XF + (size_t)(m0 + pr0 + 64) * IND + pg * 8;

// prefetch xf block (ibn) into parity slot (ibn&1)
#define PREFETCH_XF(ibn)                                                       \
    {   const uint32_t dstb = sb + OFF_XF + (uint32_t)(((ibn) & 1) * 16384);   \
        cp_async16(dstb + psoff0, gX0 + (ibn) * 64);                           \
        cp_async16(dstb + psoff1, gX1 + (ibn) * 64);                           \
    }

    // ---- g_W-independent prologue work (overlaps other CTAs' packing) ----
    PREFETCH_XF(0);
    PREFETCH_XF(1);

    // kb tables (f32 for epilogue, bf16 for mainloop scales)
    if (tid < 128) {
        const float2 tt = *reinterpret_cast<const float2*>(
            x + (size_t)(m0 + tid) * ROWLEN);
        const float t0 = tt.x, t1 = tt.y;
        float u[5], v[5];
        u[0] = 1.0f; u[1] = t0; u[2] = t0 * t0;
        { float a = t0 - 0.33f; a = a > 0 ? a : 0; u[3] = a * a; }
        { float a = t0 - 0.66f; a = a > 0 ? a : 0; u[4] = a * a; }
        v[0] = 1.0f; v[1] = t1; v[2] = t1 * t1;
        { float a = t1 - 0.33f; a = a > 0 ? a : 0; v[3] = a * a; }
        { float a = t1 - 0.66f; a = a > 0 ? a : 0; v[4] = a * a; }

        float* kbf = reinterpret_cast<float*>(smem + OFF_KBF);
        uint16_t* kbs = reinterpret_cast<uint16_t*>(smem + OFF_KBS);
#pragma unroll
        for (int i = 0; i < 5; ++i)
#pragma unroll
            for (int j = 0; j < 5; ++j) {
                const int d = i * 5 + j;
                const float kv = u[i] * v[j];
                kbf[d * 128 + tid] = kv;
                kbs[d * 128 + tid] = f2bf(kv);
            }
    }

    // ---- spin until all 32 i-blocks of my o-block are packed ----
    if (tid == 0) {
        while (atomicAdd(&g_cnt[blockIdx.y], 0u) < 32u) { }
    }
    __syncthreads();
    __threadfence();   // acquire: order packed g_W ahead of our B loads

    // B prologue: chunks 0..3 -> stages 0..3 (scratch region is dead now)
#pragma unroll
    for (int f = 0; f < 4; ++f) {
        const uint32_t dst = sb + OFF_BST + f * STAGE_B;
        cp_async16(dst + psoff0, gB0 + (size_t)f * 64);
        cp_async16(dst + psoff1, gB1 + (size_t)f * 64);
    }
    asm volatile("cp.async.commit_group;" ::: "memory");

    // ======================= consumer geometry ==============================
    const int arow = wm * 32 + (lid & 15);
    const uint32_t a_sz = (uint32_t)((arow & 7) << 4);
    const uint32_t a_k  = (uint32_t)((lid >> 4) * 16);
    const int brow = wn * 32 + ((lid >> 4) << 3) + (lid & 7);
    const uint32_t b_sz = (uint32_t)((lid & 7) << 4);
    const uint32_t b_k  = (uint32_t)(((lid >> 3) & 1) * 16);

    float c[2][4][4];
#pragma unroll
    for (int mt = 0; mt < 2; ++mt)
#pragma unroll
        for (int nt = 0; nt < 4; ++nt)
#pragma unroll
            for (int i = 0; i < 4; ++i) c[mt][nt][i] = 0.0f;

    const float*    kbf = reinterpret_cast<const float*>(smem + OFF_KBF);
    const uint16_t* kbs = reinterpret_cast<const uint16_t*>(smem + OFF_KBS);
    const int krow0 = wm * 32 + (lid >> 2);   // fragment row (+mt*16)

    uint32_t xfA[4][2][4];   // raw xf frags [ks][mt][reg], persists across d
    uint32_t aS[2][4];       // scaled frags for current ks
    uint32_t bF[2][2][4];    // B frags, double buffered

#define LOAD_XFA(ibcur)                                                        \
    {   const uint32_t base = sb + OFF_XF + (uint32_t)(((ibcur) & 1) * 16384); \
        _Pragma("unroll")                                                      \
        for (int ks = 0; ks < 4; ++ks)                                         \
            _Pragma("unroll")                                                  \
            for (int mt = 0; mt < 2; ++mt)                                     \
                ldsm_x4(xfA[ks][mt], base + (uint32_t)(arow + mt * 16) * 128   \
                        + (((uint32_t)(ks * 32) + a_k) ^ a_sz));               \
    }

#define LOAD_B(buf, kk)                                                        \
    {   const uint32_t kof = (uint32_t)((kk) * 32);                            \
        _Pragma("unroll")                                                      \
        for (int np = 0; np < 2; ++np)                                         \
            ldsm_x4(bF[buf][np], stB + (uint32_t)(brow + np * 16) * 128 +      \
                                 ((kof + b_k) ^ b_sz));                        \
    }

#define CONSUME(f, dcur, ibcur)                                                \
    {   const uint32_t stB = sb + OFF_BST + ((f) & 7) * STAGE_B;               \
        if ((dcur) == 0) LOAD_XFA(ibcur);                                      \
        uint32_t kLo[2], kHi[2];                                               \
        _Pragma("unroll")                                                      \
        for (int mt = 0; mt < 2; ++mt) {                                       \
            const int r = krow0 + mt * 16;                                     \
            kLo[mt] = (uint32_t)kbs[(dcur) * 128 + r] * 0x10001u;              \
            kHi[mt] = (uint32_t)kbs[(dcur) * 128 + r + 8] * 0x10001u;          \
        }                                                                      \
        LOAD_B(0, 0);                                                          \
        _Pragma("unroll")                                                      \
        for (int ks = 0; ks < 4; ++ks) {                                       \
            const int cur = ks & 1;                                            \
            if (ks < 3) LOAD_B(cur ^ 1, ks + 1);                               \
            _Pragma("unroll")                                                  \
            for (int mt = 0; mt < 2; ++mt) {                                   \
                aS[mt][0] = mul_bf16x2(xfA[ks][mt][0], kLo[mt]);               \
                aS[mt][1] = mul_bf16x2(xfA[ks][mt][1], kHi[mt]);               \
                aS[mt][2] = mul_bf16x2(xfA[ks][mt][2], kLo[mt]);               \
                aS[mt][3] = mul_bf16x2(xfA[ks][mt][3], kHi[mt]);               \
            }                                                                  \
            _Pragma("unroll")                                                  \
            for (int mt = 0; mt < 2; ++mt)                                     \
                _Pragma("unroll")                                              \
                for (int np = 0; np < 2; ++np) {                               \
                    mma16816(c[mt][2*np],   aS[mt], bF[cur][np][0], bF[cur][np][1]); \
                    mma16816(c[mt][2*np+1], aS[mt], bF[cur][np][2], bF[cur][np][3]); \
                }                                                              \
        }                                                                      \
    }

    int dcnt = 0, ibc = 0, ibp = 1;

    // === main loop: 4 chunks/epoch, race-free ordering, 50 barriers =========
    for (int e = 0; e < NCH; e += 4) {
        asm volatile("cp.async.wait_group 0;" ::: "memory");
        __syncthreads();

#pragma unroll
        for (int k = 4; k < 8; ++k) {
            const int f = e + k;
            if (f < NCH) {
                const uint32_t dst = sb + OFF_BST + (f & 7) * STAGE_B;
                cp_async16(dst + psoff0, gB0 + (size_t)f * 64);
                cp_async16(dst + psoff1, gB1 + (size_t)f * 64);
            }
        }
        {   // xf block needed next epoch: at most one new ib
            const int ibn = (e + 7) / 25;
            if (ibn > ibp && ibn < 8) { PREFETCH_XF(ibn); ibp = ibn; }
        }
        asm volatile("cp.async.commit_group;" ::: "memory");

        CONSUME(e,     dcnt, ibc); if (++dcnt == D2) { dcnt = 0; ++ibc; }
        CONSUME(e + 1, dcnt, ibc); if (++dcnt == D2) { dcnt = 0; ++ibc; }
        CONSUME(e + 2, dcnt, ibc); if (++dcnt == D2) { dcnt = 0; ++ibc; }
        CONSUME(e + 3, dcnt, ibc); if (++dcnt == D2) { dcnt = 0; ++ibc; }
    }

    // ================= bias epilogue: c += kb(f32) @ bias^T =================
    asm volatile("cp.async.wait_group 0;" ::: "memory");
    __syncthreads();   // all fragment reads done before sbias overwrites stage 0
    float* sbias = reinterpret_cast<float*>(smem + OFF_BST);
    {
        const float* gb = bias + (size_t)n0 * D2;
        for (int i = tid; i < 128 * D2; i += 512) sbias[i] = gb[i];
    }
    __syncthreads();

    {
        const int cb0 = wn * 32 + ((lid & 3) << 1);   // local col base
#pragma unroll 1
        for (int d = 0; d < D2; ++d) {
            float kbA[2], kbB[2];
#pragma unroll
            for (int mt = 0; mt < 2; ++mt) {
                const int r = krow0 + mt * 16;
                kbA[mt] = kbf[d * 128 + r];
                kbB[mt] = kbf[d * 128 + r + 8];
            }
#pragma unroll
            for (int nt = 0; nt < 4; ++nt) {
                const int cc = cb0 + nt * 8;
                const float b0 = sbias[cc * D2 + d];
                const float b1 = sbias[(cc + 1) * D2 + d];
#pragma unroll
                for (int mt = 0; mt < 2; ++mt) {
                    c[mt][nt][0] += kbA[mt] * b0;
                    c[mt][nt][1] += kbA[mt] * b1;
                    c[mt][nt][2] += kbB[mt] * b0;
                    c[mt][nt][3] += kbB[mt] * b1;
                }
            }
        }
    }

    // ---- fused ReLU epilogue
    {
        const int rbase = m0 + wm * 32 + (lid >> 2);
        const int cbase = n0 + wn * 32 + ((lid & 3) << 1);
#pragma unroll
        for (int mt = 0; mt < 2; ++mt) {
            const int r = rbase + mt * 16;
#pragma unroll
            for (int nt = 0; nt < 4; ++nt) {
                const int cc = cbase + nt * 8;
                float2 v0, v1;
                v0.x = fmaxf(c[mt][nt][0], 0.0f);
                v0.y = fmaxf(c[mt][nt][1], 0.0f);
                v1.x = fmaxf(c[mt][nt][2], 0.0f);
                v1.y = fmaxf(c[mt][nt][3], 0.0f);
                *reinterpret_cast<float2*>(out + (size_t)r * ROWLEN + 2 + cc) = v0;
                *reinterpret_cast<float2*>(out + (size_t)(r + 8) * ROWLEN + 2 + cc) = v1;
            }
        }
    }
}

// ---------------------------------------------------------------------------
// Launch
// ---------------------------------------------------------------------------
extern "C" void kernel_launch(void* const* d_in, const int* in_sizes, int n_in,
                              void* d_out, int out_size)
{
    (void)in_sizes; (void)n_in; (void)out_size;
    const float* x    = (const float*)d_in[0];   // (4096, 514)
    const float* w    = (const float*)d_in[1];   // (512, 512, 25)
    const float* bias = (const float*)d_in[2];   // (512, 25)
    float* out = (float*)d_out;                  // (4096, 514)

    cudaFuncSetAttribute(gemm_hmma_kernel,
                         cudaFuncAttributeMaxDynamicSharedMemorySize, SMEM_GEMM);

    prep_XF_kernel<<<BATCH, 256>>>(x, out);
    gemm_hmma_kernel<<<dim3(BATCH / TILE_M, OUTD / TILE_N), 512, SMEM_GEMM>>>(
        x, w, bias, out);
}